// round 4
// baseline (speedup 1.0000x reference)
#include <cuda_runtime.h>
#include <cuda_bf16.h>
#include <math.h>
#include <stdint.h>

// Problem constants
#define SEQ   4096
#define DIM   1024
#define C3    3072
#define NHEAD 16
#define HD    64
#define SCALE 0.125f

__device__ float g_qkv[SEQ * C3];     // 48 MB
__device__ float g_att[SEQ * DIM];    // 16 MB

// ---------------------------------------------------------------------------
// Helpers
// ---------------------------------------------------------------------------
__device__ __forceinline__ float to_tf32(float x) {
    float r;
    asm("cvt.rna.tf32.f32 %0, %1;" : "=f"(r) : "f"(x));
    return r;
}
__device__ __forceinline__ uint32_t f2u(float x) { return __float_as_uint(x); }

__device__ __forceinline__ void mma_tf32(float* c,
                                         uint32_t a0, uint32_t a1, uint32_t a2, uint32_t a3,
                                         uint32_t b0, uint32_t b1) {
    asm volatile(
        "mma.sync.aligned.m16n8k8.row.col.f32.tf32.tf32.f32 "
        "{%0,%1,%2,%3}, {%4,%5,%6,%7}, {%8,%9}, {%0,%1,%2,%3};"
        : "+f"(c[0]), "+f"(c[1]), "+f"(c[2]), "+f"(c[3])
        : "r"(a0), "r"(a1), "r"(a2), "r"(a3), "r"(b0), "r"(b1));
}

// ---------------------------------------------------------------------------
// TF32 tensor-core GEMM: C[M,N] = A[M,K] @ B[N,K]^T (+bias)
// CTA tile 128x256, BK=16, 8 warps with 64x64 warp tiles (2 m x 4 n).
// Fragment-permuted smem: A fragments load as LDS.128, B as LDS.64,
// both bank-conflict-free. 2-stage smem double buffer, one barrier/iter.
//
// A-perm layout (per 16-row x 8-k unit): float idx =
//   ((m>>4)*2 + (k>>3))*128 + ((m&7)*4 + (k&3))*4 + ((k>>2)&1)*2 + ((m>>3)&1)
// B-perm layout (per 8-row x 8-k unit): float idx =
//   ((n>>3)*2 + (k>>3))*64 + ((n&7)*4 + (k&3))*2 + ((k>>2)&1)
// ---------------------------------------------------------------------------
#define GBM 128
#define GBN 256
#define GBK 16
#define A_FLOATS (GBM * GBK)     // 2048
#define B_FLOATS (GBN * GBK)     // 4096

__global__ __launch_bounds__(256, 1)
void gemm_tf32(const float* __restrict__ A, const float* __restrict__ B,
               const float* __restrict__ bias, float* __restrict__ C,
               int M, int N, int K)
{
    __shared__ float As[2][A_FLOATS];
    __shared__ float Bs[2][B_FLOATS];

    const int bx = blockIdx.x;        // N tile
    const int by = blockIdx.y;        // M tile
    const int tid = threadIdx.x;
    const int lane = tid & 31;
    const int wid = tid >> 5;
    const int wm = wid & 1;           // 0..1 (64-row block)
    const int wn = wid >> 1;          // 0..3 (64-col block)

    const float* Ab = A + (size_t)(by * GBM) * K;
    const float* Bb = B + (size_t)(bx * GBN) * K;

    float acc[4][8][4];
#pragma unroll
    for (int mi = 0; mi < 4; mi++)
#pragma unroll
        for (int ni = 0; ni < 8; ni++)
#pragma unroll
            for (int r = 0; r < 4; r++) acc[mi][ni][r] = 0.f;

    // Fill helper indices: A has 512 float4 (2/thread), B has 1024 (4/thread).
    // t -> row = t>>2, c4 = t&3 (k-group of 4)
    // Prologue: fill stage 0
    {
#pragma unroll
        for (int p = 0; p < 2; p++) {
            const int t = tid + p * 256;
            const int m = t >> 2, c4 = t & 3;
            float4 v = *(const float4*)&Ab[(size_t)m * K + c4 * 4];
            const int base = ((m >> 4) * 2 + (c4 >> 1)) * 128 + (m & 7) * 16 +
                             (c4 & 1) * 2 + ((m >> 3) & 1);
            As[0][base + 0]  = to_tf32(v.x);
            As[0][base + 4]  = to_tf32(v.y);
            As[0][base + 8]  = to_tf32(v.z);
            As[0][base + 12] = to_tf32(v.w);
        }
#pragma unroll
        for (int p = 0; p < 4; p++) {
            const int t = tid + p * 256;
            const int n = t >> 2, c4 = t & 3;
            float4 v = *(const float4*)&Bb[(size_t)n * K + c4 * 4];
            const int base = ((n >> 3) * 2 + (c4 >> 1)) * 64 + (n & 7) * 8 + (c4 & 1);
            Bs[0][base + 0] = to_tf32(v.x);
            Bs[0][base + 2] = to_tf32(v.y);
            Bs[0][base + 4] = to_tf32(v.z);
            Bs[0][base + 6] = to_tf32(v.w);
        }
    }
    __syncthreads();

    const int nIter = K / GBK;
    for (int it = 0; it < nIter; it++) {
        const int cur = it & 1;
        const int nxt = cur ^ 1;

        // Issue next-tile global loads early
        float4 aN[2], bN[4];
        if (it + 1 < nIter) {
            const int k0 = (it + 1) * GBK;
#pragma unroll
            for (int p = 0; p < 2; p++) {
                const int t = tid + p * 256;
                aN[p] = *(const float4*)&Ab[(size_t)(t >> 2) * K + k0 + (t & 3) * 4];
            }
#pragma unroll
            for (int p = 0; p < 4; p++) {
                const int t = tid + p * 256;
                bN[p] = *(const float4*)&Bb[(size_t)(t >> 2) * K + k0 + (t & 3) * 4];
            }
        }

        // Compute current tile
        const float* Ac = As[cur];
        const float* Bc = Bs[cur];
#pragma unroll
        for (int ks = 0; ks < 2; ks++) {
            uint32_t af[4][4];
#pragma unroll
            for (int mi = 0; mi < 4; mi++) {
                const int tile = (wm * 4 + mi) * 2 + ks;
                float4 v = *(const float4*)&Ac[tile * 128 + lane * 4];
                af[mi][0] = f2u(v.x); af[mi][1] = f2u(v.y);
                af[mi][2] = f2u(v.z); af[mi][3] = f2u(v.w);
            }
            uint32_t bf[8][2];
#pragma unroll
            for (int ni = 0; ni < 8; ni++) {
                const int tile = (wn * 8 + ni) * 2 + ks;
                float2 v = *(const float2*)&Bc[tile * 64 + lane * 2];
                bf[ni][0] = f2u(v.x); bf[ni][1] = f2u(v.y);
            }
#pragma unroll
            for (int mi = 0; mi < 4; mi++)
#pragma unroll
                for (int ni = 0; ni < 8; ni++)
                    mma_tf32(acc[mi][ni], af[mi][0], af[mi][1], af[mi][2], af[mi][3],
                             bf[ni][0], bf[ni][1]);
        }

        // Store next tile (permuted + tf32)
        if (it + 1 < nIter) {
#pragma unroll
            for (int p = 0; p < 2; p++) {
                const int t = tid + p * 256;
                const int m = t >> 2, c4 = t & 3;
                const int base = ((m >> 4) * 2 + (c4 >> 1)) * 128 + (m & 7) * 16 +
                                 (c4 & 1) * 2 + ((m >> 3) & 1);
                As[nxt][base + 0]  = to_tf32(aN[p].x);
                As[nxt][base + 4]  = to_tf32(aN[p].y);
                As[nxt][base + 8]  = to_tf32(aN[p].z);
                As[nxt][base + 12] = to_tf32(aN[p].w);
            }
#pragma unroll
            for (int p = 0; p < 4; p++) {
                const int t = tid + p * 256;
                const int n = t >> 2, c4 = t & 3;
                const int base = ((n >> 3) * 2 + (c4 >> 1)) * 64 + (n & 7) * 8 + (c4 & 1);
                Bs[nxt][base + 0] = to_tf32(bN[p].x);
                Bs[nxt][base + 2] = to_tf32(bN[p].y);
                Bs[nxt][base + 4] = to_tf32(bN[p].z);
                Bs[nxt][base + 6] = to_tf32(bN[p].w);
            }
        }
        __syncthreads();
    }

    // Epilogue
    const int g = lane >> 2;
    const int tig = lane & 3;
#pragma unroll
    for (int mi = 0; mi < 4; mi++) {
#pragma unroll
        for (int ni = 0; ni < 8; ni++) {
            const int row0 = by * GBM + wm * 64 + mi * 16 + g;
            const int col = bx * GBN + wn * 64 + ni * 8 + 2 * tig;
            float b0 = 0.f, b1 = 0.f;
            if (bias) { b0 = bias[col]; b1 = bias[col + 1]; }
            *(float2*)&C[(size_t)row0 * N + col] =
                make_float2(acc[mi][ni][0] + b0, acc[mi][ni][1] + b1);
            *(float2*)&C[(size_t)(row0 + 8) * N + col] =
                make_float2(acc[mi][ni][2] + b0, acc[mi][ni][3] + b1);
        }
    }
}

// ---------------------------------------------------------------------------
// Flash attention, TF32 mma.sync (unchanged from R2 — known good at ~597us)
// ---------------------------------------------------------------------------
#define AQ 64
#define AK 64
#define QKS 68
#define VSS 72
#define ATTN_SMEM ((3 * 64 * QKS + 64 * VSS) * 4)

__global__ __launch_bounds__(128, 2)
void attn_tf32(const float* __restrict__ qkv, float* __restrict__ out)
{
    extern __shared__ float sm[];
    float* Qs = sm;
    float* Ks = Qs + 64 * QKS;
    float* Ps = Ks + 64 * QKS;
    float* Vs = Ps + 64 * QKS;

    const int h = blockIdx.y;
    const int qb = blockIdx.x;
    const int tid = threadIdx.x;
    const int lane = tid & 31;
    const int w = tid >> 5;
    const int g = lane >> 2;
    const int tig = lane & 3;

    const int qcol = h * HD;
    const int kcol = DIM + h * HD;
    const int vcol = 2 * DIM + h * HD;

    for (int idx = tid; idx < AQ * HD / 4; idx += 128) {
        const int r = idx >> 4;
        const int c4 = idx & 15;
        float4 v = *(const float4*)&qkv[(size_t)(qb * AQ + r) * C3 + qcol + c4 * 4];
        Qs[r * QKS + c4 * 4 + 0] = to_tf32(v.x * SCALE);
        Qs[r * QKS + c4 * 4 + 1] = to_tf32(v.y * SCALE);
        Qs[r * QKS + c4 * 4 + 2] = to_tf32(v.z * SCALE);
        Qs[r * QKS + c4 * 4 + 3] = to_tf32(v.w * SCALE);
    }
    __syncthreads();

    uint32_t qf[8][4];
#pragma unroll
    for (int ks = 0; ks < 8; ks++) {
        const int kb = ks * 8;
        const int rb = w * 16;
        qf[ks][0] = f2u(Qs[(rb + g) * QKS + kb + tig]);
        qf[ks][1] = f2u(Qs[(rb + g + 8) * QKS + kb + tig]);
        qf[ks][2] = f2u(Qs[(rb + g) * QKS + kb + tig + 4]);
        qf[ks][3] = f2u(Qs[(rb + g + 8) * QKS + kb + tig + 4]);
    }

    float m0 = -1e30f, m1 = -1e30f, l0 = 0.f, l1 = 0.f;
    float o[8][4];
#pragma unroll
    for (int ni = 0; ni < 8; ni++)
#pragma unroll
        for (int r = 0; r < 4; r++) o[ni][r] = 0.f;

    for (int kt = 0; kt < SEQ / AK; kt++) {
        __syncthreads();
        for (int idx = tid; idx < AK * HD / 4; idx += 128) {
            const int r = idx >> 4;
            const int c4 = idx & 15;
            const size_t ro = (size_t)(kt * AK + r) * C3;
            float4 kv = *(const float4*)&qkv[ro + kcol + c4 * 4];
            Ks[r * QKS + c4 * 4 + 0] = to_tf32(kv.x);
            Ks[r * QKS + c4 * 4 + 1] = to_tf32(kv.y);
            Ks[r * QKS + c4 * 4 + 2] = to_tf32(kv.z);
            Ks[r * QKS + c4 * 4 + 3] = to_tf32(kv.w);
            float4 vv = *(const float4*)&qkv[ro + vcol + c4 * 4];
            Vs[r * VSS + c4 * 4 + 0] = to_tf32(vv.x);
            Vs[r * VSS + c4 * 4 + 1] = to_tf32(vv.y);
            Vs[r * VSS + c4 * 4 + 2] = to_tf32(vv.z);
            Vs[r * VSS + c4 * 4 + 3] = to_tf32(vv.w);
        }
        __syncthreads();

        float s[8][4];
#pragma unroll
        for (int ni = 0; ni < 8; ni++)
#pragma unroll
            for (int r = 0; r < 4; r++) s[ni][r] = 0.f;

#pragma unroll
        for (int ks = 0; ks < 8; ks++) {
            const int kb = ks * 8;
            uint32_t bf[8][2];
#pragma unroll
            for (int ni = 0; ni < 8; ni++) {
                bf[ni][0] = f2u(Ks[(ni * 8 + g) * QKS + kb + tig]);
                bf[ni][1] = f2u(Ks[(ni * 8 + g) * QKS + kb + tig + 4]);
            }
#pragma unroll
            for (int ni = 0; ni < 8; ni++)
                mma_tf32(s[ni], qf[ks][0], qf[ks][1], qf[ks][2], qf[ks][3],
                         bf[ni][0], bf[ni][1]);
        }

        float mx0 = -1e30f, mx1 = -1e30f;
#pragma unroll
        for (int ni = 0; ni < 8; ni++) {
            mx0 = fmaxf(mx0, fmaxf(s[ni][0], s[ni][1]));
            mx1 = fmaxf(mx1, fmaxf(s[ni][2], s[ni][3]));
        }
#pragma unroll
        for (int off = 1; off < 4; off <<= 1) {
            mx0 = fmaxf(mx0, __shfl_xor_sync(0xffffffffu, mx0, off));
            mx1 = fmaxf(mx1, __shfl_xor_sync(0xffffffffu, mx1, off));
        }
        const float nm0 = fmaxf(m0, mx0);
        const float nm1 = fmaxf(m1, mx1);
        const float al0 = __expf(m0 - nm0);
        const float al1 = __expf(m1 - nm1);
        m0 = nm0; m1 = nm1;

        float rs0 = 0.f, rs1 = 0.f;
        const int pr0 = (w * 16 + g) * QKS;
        const int pr1 = (w * 16 + g + 8) * QKS;
#pragma unroll
        for (int ni = 0; ni < 8; ni++) {
            const float p0 = __expf(s[ni][0] - nm0);
            const float p1 = __expf(s[ni][1] - nm0);
            const float p2 = __expf(s[ni][2] - nm1);
            const float p3 = __expf(s[ni][3] - nm1);
            rs0 += p0 + p1;
            rs1 += p2 + p3;
            const int c = ni * 8 + 2 * tig;
            Ps[pr0 + c] = p0; Ps[pr0 + c + 1] = p1;
            Ps[pr1 + c] = p2; Ps[pr1 + c + 1] = p3;
        }
#pragma unroll
        for (int off = 1; off < 4; off <<= 1) {
            rs0 += __shfl_xor_sync(0xffffffffu, rs0, off);
            rs1 += __shfl_xor_sync(0xffffffffu, rs1, off);
        }
        l0 = l0 * al0 + rs0;
        l1 = l1 * al1 + rs1;
#pragma unroll
        for (int ni = 0; ni < 8; ni++) {
            o[ni][0] *= al0; o[ni][1] *= al0;
            o[ni][2] *= al1; o[ni][3] *= al1;
        }
        __syncwarp();

#pragma unroll
        for (int ks = 0; ks < 8; ks++) {
            const int kb = ks * 8;
            uint32_t a0 = f2u(Ps[pr0 + kb + tig]);
            uint32_t a1 = f2u(Ps[pr1 + kb + tig]);
            uint32_t a2 = f2u(Ps[pr0 + kb + tig + 4]);
            uint32_t a3 = f2u(Ps[pr1 + kb + tig + 4]);
#pragma unroll
            for (int ni = 0; ni < 8; ni++) {
                uint32_t b0 = f2u(Vs[(kb + tig) * VSS + ni * 8 + g]);
                uint32_t b1 = f2u(Vs[(kb + tig + 4) * VSS + ni * 8 + g]);
                mma_tf32(o[ni], a0, a1, a2, a3, b0, b1);
            }
        }
    }

    const float inv0 = 1.f / l0;
    const float inv1 = 1.f / l1;
    const int row0 = qb * AQ + w * 16 + g;
#pragma unroll
    for (int ni = 0; ni < 8; ni++) {
        const int col = h * HD + ni * 8 + 2 * tig;
        *(float2*)&out[(size_t)row0 * DIM + col] =
            make_float2(o[ni][0] * inv0, o[ni][1] * inv0);
        *(float2*)&out[(size_t)(row0 + 8) * DIM + col] =
            make_float2(o[ni][2] * inv1, o[ni][3] * inv1);
    }
}

// ---------------------------------------------------------------------------
extern "C" void kernel_launch(void* const* d_in, const int* in_sizes, int n_in,
                              void* d_out, int out_size)
{
    const float* x      = (const float*)d_in[0];
    const float* W_qkv  = (const float*)d_in[1];
    const float* W_proj = (const float*)d_in[2];
    const float* b_proj = (const float*)d_in[3];
    float* out = (float*)d_out;

    float* qkv; cudaGetSymbolAddress((void**)&qkv, g_qkv);
    float* att; cudaGetSymbolAddress((void**)&att, g_att);

    cudaFuncSetAttribute(attn_tf32,
                         cudaFuncAttributeMaxDynamicSharedMemorySize, ATTN_SMEM);

    // 1) qkv = x @ W_qkv^T
    {
        dim3 grid(C3 / GBN, SEQ / GBM);
        gemm_tf32<<<grid, 256>>>(x, W_qkv, nullptr, qkv, SEQ, C3, C3);
    }
    // 2) attention
    {
        dim3 grid(SEQ / AQ, NHEAD);
        attn_tf32<<<grid, 128, ATTN_SMEM>>>(qkv, att);
    }
    // 3) out = att @ W_proj^T + b_proj
    {
        dim3 grid(DIM / GBN, SEQ / GBM);
        gemm_tf32<<<grid, 256>>>(att, W_proj, b_proj, out, SEQ, DIM, DIM);
    }
}

// round 6
// speedup vs baseline: 1.4126x; 1.4126x over previous
#include <cuda_runtime.h>
#include <cuda_fp16.h>
#include <math.h>
#include <stdint.h>

// Problem constants
#define SEQ   4096
#define DIM   1024
#define C3    3072
#define NHEAD 16
#define HD    64
#define SCALE 0.125f

__device__ float g_qkv[SEQ * C3];     // 48 MB
__device__ float g_att[SEQ * DIM];    // 16 MB

// ---------------------------------------------------------------------------
// Helpers
// ---------------------------------------------------------------------------
__device__ __forceinline__ void mma_f16(float* c,
                                        uint32_t a0, uint32_t a1, uint32_t a2, uint32_t a3,
                                        uint32_t b0, uint32_t b1) {
    asm volatile(
        "mma.sync.aligned.m16n8k16.row.col.f32.f16.f16.f32 "
        "{%0,%1,%2,%3}, {%4,%5,%6,%7}, {%8,%9}, {%0,%1,%2,%3};"
        : "+f"(c[0]), "+f"(c[1]), "+f"(c[2]), "+f"(c[3])
        : "r"(a0), "r"(a1), "r"(a2), "r"(a3), "r"(b0), "r"(b1));
}

__device__ __forceinline__ uint2 f4_to_h4(float4 v) {
    __half2 a = __floats2half2_rn(v.x, v.y);
    __half2 b = __floats2half2_rn(v.z, v.w);
    uint2 r;
    r.x = *(uint32_t*)&a;
    r.y = *(uint32_t*)&b;
    return r;
}

__device__ __forceinline__ uint32_t ldh2(const __half* p) {
    return *(const uint32_t*)p;
}

// ---------------------------------------------------------------------------
// FP16 tensor-core GEMM: C[M,N] = A[M,K] @ B[N,K]^T (+bias), fp32 accumulate.
// 256 threads = 8 warps (4 m x 2 n), CTA tile 128x128, BK=32 (halves).
// Warp tile 32x64 -> mma grid 2(m) x 8(n), 2 k-steps of 16.
// smem stride 40 halves (rows hold 32 halves): fragment word addr = row*20+tig,
// (20g+tig) mod 32 distinct -> conflict-free.
// ---------------------------------------------------------------------------
#define BM 128
#define BN 128
#define BKH 32
#define SH 40

__global__ __launch_bounds__(256, 2)
void gemm_f16(const float* __restrict__ A, const float* __restrict__ B,
              const float* __restrict__ bias, float* __restrict__ C,
              int M, int N, int K)
{
    __shared__ __align__(16) __half As[BM * SH];
    __shared__ __align__(16) __half Bs[BN * SH];

    const int bx = blockIdx.x;        // N tile
    const int by = blockIdx.y;        // M tile
    const int tid = threadIdx.x;
    const int lane = tid & 31;
    const int wid = tid >> 5;
    const int wm = wid >> 1;          // 0..3
    const int wn = wid & 1;           // 0..1
    const int g = lane >> 2;          // 0..7
    const int tig = lane & 3;         // 0..3

    const int lr = tid >> 3;          // 0..31
    const int lc = tid & 7;           // 0..7

    const float* Ab = A + (size_t)(by * BM) * K;
    const float* Bb = B + (size_t)(bx * BN) * K;

    float acc[2][8][4];
#pragma unroll
    for (int mi = 0; mi < 2; mi++)
#pragma unroll
        for (int ni = 0; ni < 8; ni++)
#pragma unroll
            for (int r = 0; r < 4; r++) acc[mi][ni][r] = 0.f;

    // Prologue: fill tile 0
#pragma unroll
    for (int p = 0; p < 4; p++) {
        const int r = lr + p * 32;
        *(uint2*)&As[r * SH + lc * 4] = f4_to_h4(*(const float4*)&Ab[(size_t)r * K + lc * 4]);
        *(uint2*)&Bs[r * SH + lc * 4] = f4_to_h4(*(const float4*)&Bb[(size_t)r * K + lc * 4]);
    }
    __syncthreads();

    const int nIter = K / BKH;
    for (int it = 0; it < nIter; it++) {
        // Prefetch next tile into registers
        uint2 aN[4], bN[4];
        if (it + 1 < nIter) {
            const int k0 = (it + 1) * BKH;
#pragma unroll
            for (int p = 0; p < 4; p++) {
                const int r = lr + p * 32;
                aN[p] = f4_to_h4(*(const float4*)&Ab[(size_t)r * K + k0 + lc * 4]);
                bN[p] = f4_to_h4(*(const float4*)&Bb[(size_t)r * K + k0 + lc * 4]);
            }
        }

        // Compute current tile: 2 k-steps of 16
#pragma unroll
        for (int ks = 0; ks < 2; ks++) {
            const int kb = ks * 16;
            uint32_t af[2][4];
#pragma unroll
            for (int mi = 0; mi < 2; mi++) {
                const int rbm = wm * 32 + mi * 16;
                af[mi][0] = ldh2(&As[(rbm + g) * SH + kb + 2 * tig]);
                af[mi][1] = ldh2(&As[(rbm + g + 8) * SH + kb + 2 * tig]);
                af[mi][2] = ldh2(&As[(rbm + g) * SH + kb + 8 + 2 * tig]);
                af[mi][3] = ldh2(&As[(rbm + g + 8) * SH + kb + 8 + 2 * tig]);
            }
            uint32_t bf[8][2];
#pragma unroll
            for (int ni = 0; ni < 8; ni++) {
                const int nb = wn * 64 + ni * 8;
                bf[ni][0] = ldh2(&Bs[(nb + g) * SH + kb + 2 * tig]);
                bf[ni][1] = ldh2(&Bs[(nb + g) * SH + kb + 8 + 2 * tig]);
            }
#pragma unroll
            for (int mi = 0; mi < 2; mi++)
#pragma unroll
                for (int ni = 0; ni < 8; ni++)
                    mma_f16(acc[mi][ni], af[mi][0], af[mi][1], af[mi][2], af[mi][3],
                            bf[ni][0], bf[ni][1]);
        }
        __syncthreads();

        if (it + 1 < nIter) {
#pragma unroll
            for (int p = 0; p < 4; p++) {
                const int r = lr + p * 32;
                *(uint2*)&As[r * SH + lc * 4] = aN[p];
                *(uint2*)&Bs[r * SH + lc * 4] = bN[p];
            }
            __syncthreads();
        }
    }

    // Epilogue
#pragma unroll
    for (int mi = 0; mi < 2; mi++) {
#pragma unroll
        for (int ni = 0; ni < 8; ni++) {
            const int row0 = by * BM + wm * 32 + mi * 16 + g;
            const int col = bx * BN + wn * 64 + ni * 8 + 2 * tig;
            float b0 = 0.f, b1 = 0.f;
            if (bias) { b0 = bias[col]; b1 = bias[col + 1]; }
            *(float2*)&C[(size_t)row0 * N + col] =
                make_float2(acc[mi][ni][0] + b0, acc[mi][ni][1] + b1);
            *(float2*)&C[(size_t)(row0 + 8) * N + col] =
                make_float2(acc[mi][ni][2] + b0, acc[mi][ni][3] + b1);
        }
    }
}

// ---------------------------------------------------------------------------
// Flash attention, fp16 mma (fp32 accum/softmax). Grid (SEQ/64, NHEAD),
// 128 threads (4 warps), each warp 16 q-rows. 64-key tiles.
// All smem tiles stride 72 halves (rows hold 64 halves + pad):
//   word addr = row*36 + tig (+k/2); (36g) mod 32 = 4g -> conflict-free.
// Vs is transposed [hd][key] so PV B-frags are contiguous half2 along keys.
// Smem = 4 * 64*72*2 = 36 KB.
// ---------------------------------------------------------------------------
#define AQ 64
#define AK 64
#define AST 72

__global__ __launch_bounds__(128, 4)
void attn_f16(const float* __restrict__ qkv, float* __restrict__ out)
{
    __shared__ __align__(16) __half Qs[AQ * AST];
    __shared__ __align__(16) __half Ks[AK * AST];
    __shared__ __align__(16) __half Ps[AQ * AST];
    __shared__ __align__(16) __half Vs[HD * AST];   // [hd][key]

    const int h = blockIdx.y;
    const int qb = blockIdx.x;
    const int tid = threadIdx.x;
    const int lane = tid & 31;
    const int w = tid >> 5;
    const int g = lane >> 2;
    const int tig = lane & 3;

    const int qcol = h * HD;
    const int kcol = DIM + h * HD;
    const int vcol = 2 * DIM + h * HD;

    // Load Q (scaled). 64 rows x 16 float4; 8 per thread.
    for (int idx = tid; idx < AQ * HD / 4; idx += 128) {
        const int r = idx >> 4;
        const int c4 = idx & 15;
        float4 v = *(const float4*)&qkv[(size_t)(qb * AQ + r) * C3 + qcol + c4 * 4];
        v.x *= SCALE; v.y *= SCALE; v.z *= SCALE; v.w *= SCALE;
        *(uint2*)&Qs[r * AST + c4 * 4] = f4_to_h4(v);
    }
    __syncthreads();

    // Hoist Q fragments: 4 k-steps of 16
    uint32_t qf[4][4];
    const int rb = w * 16;
#pragma unroll
    for (int ks = 0; ks < 4; ks++) {
        const int kb = ks * 16;
        qf[ks][0] = ldh2(&Qs[(rb + g) * AST + kb + 2 * tig]);
        qf[ks][1] = ldh2(&Qs[(rb + g + 8) * AST + kb + 2 * tig]);
        qf[ks][2] = ldh2(&Qs[(rb + g) * AST + kb + 8 + 2 * tig]);
        qf[ks][3] = ldh2(&Qs[(rb + g + 8) * AST + kb + 8 + 2 * tig]);
    }

    float m0 = -1e30f, m1 = -1e30f, l0 = 0.f, l1 = 0.f;
    float o[8][4];
#pragma unroll
    for (int ni = 0; ni < 8; ni++)
#pragma unroll
        for (int r = 0; r < 4; r++) o[ni][r] = 0.f;

    for (int kt = 0; kt < SEQ / AK; kt++) {
        __syncthreads();
        // Load K rows; V transposed ([hd][key])
        for (int idx = tid; idx < AK * HD / 4; idx += 128) {
            const int r = idx >> 4;
            const int c4 = idx & 15;
            const size_t ro = (size_t)(kt * AK + r) * C3;
            float4 kv = *(const float4*)&qkv[ro + kcol + c4 * 4];
            *(uint2*)&Ks[r * AST + c4 * 4] = f4_to_h4(kv);
            float4 vv = *(const float4*)&qkv[ro + vcol + c4 * 4];
            Vs[(c4 * 4 + 0) * AST + r] = __float2half_rn(vv.x);
            Vs[(c4 * 4 + 1) * AST + r] = __float2half_rn(vv.y);
            Vs[(c4 * 4 + 2) * AST + r] = __float2half_rn(vv.z);
            Vs[(c4 * 4 + 3) * AST + r] = __float2half_rn(vv.w);
        }
        __syncthreads();

        // S = Q K^T : 16x64 per warp
        float s[8][4];
#pragma unroll
        for (int ni = 0; ni < 8; ni++)
#pragma unroll
            for (int r = 0; r < 4; r++) s[ni][r] = 0.f;

#pragma unroll
        for (int ks = 0; ks < 4; ks++) {
            const int kb = ks * 16;
            uint32_t bf[8][2];
#pragma unroll
            for (int ni = 0; ni < 8; ni++) {
                bf[ni][0] = ldh2(&Ks[(ni * 8 + g) * AST + kb + 2 * tig]);
                bf[ni][1] = ldh2(&Ks[(ni * 8 + g) * AST + kb + 8 + 2 * tig]);
            }
#pragma unroll
            for (int ni = 0; ni < 8; ni++)
                mma_f16(s[ni], qf[ks][0], qf[ks][1], qf[ks][2], qf[ks][3],
                        bf[ni][0], bf[ni][1]);
        }

        // Online softmax (rows g and g+8 of this warp's 16)
        float mx0 = -1e30f, mx1 = -1e30f;
#pragma unroll
        for (int ni = 0; ni < 8; ni++) {
            mx0 = fmaxf(mx0, fmaxf(s[ni][0], s[ni][1]));
            mx1 = fmaxf(mx1, fmaxf(s[ni][2], s[ni][3]));
        }
#pragma unroll
        for (int off = 1; off < 4; off <<= 1) {
            mx0 = fmaxf(mx0, __shfl_xor_sync(0xffffffffu, mx0, off));
            mx1 = fmaxf(mx1, __shfl_xor_sync(0xffffffffu, mx1, off));
        }
        const float nm0 = fmaxf(m0, mx0);
        const float nm1 = fmaxf(m1, mx1);
        const float al0 = __expf(m0 - nm0);
        const float al1 = __expf(m1 - nm1);
        m0 = nm0; m1 = nm1;

        float rs0 = 0.f, rs1 = 0.f;
        const int pr0 = (w * 16 + g) * AST;
        const int pr1 = (w * 16 + g + 8) * AST;
#pragma unroll
        for (int ni = 0; ni < 8; ni++) {
            const float p0 = __expf(s[ni][0] - nm0);
            const float p1 = __expf(s[ni][1] - nm0);
            const float p2 = __expf(s[ni][2] - nm1);
            const float p3 = __expf(s[ni][3] - nm1);
            rs0 += p0 + p1;
            rs1 += p2 + p3;
            const int c = ni * 8 + 2 * tig;
            __half2 h01 = __floats2half2_rn(p0, p1);
            __half2 h23 = __floats2half2_rn(p2, p3);
            *(uint32_t*)&Ps[pr0 + c] = *(uint32_t*)&h01;
            *(uint32_t*)&Ps[pr1 + c] = *(uint32_t*)&h23;
        }
#pragma unroll
        for (int off = 1; off < 4; off <<= 1) {
            rs0 += __shfl_xor_sync(0xffffffffu, rs0, off);
            rs1 += __shfl_xor_sync(0xffffffffu, rs1, off);
        }
        l0 = l0 * al0 + rs0;
        l1 = l1 * al1 + rs1;
#pragma unroll
        for (int ni = 0; ni < 8; ni++) {
            o[ni][0] *= al0; o[ni][1] *= al0;
            o[ni][2] *= al1; o[ni][3] *= al1;
        }
        __syncwarp();   // Ps rows warp-private

        // O += P V : A from Ps, B from Vs[hd][key]
#pragma unroll
        for (int ks = 0; ks < 4; ks++) {
            const int kb = ks * 16;
            uint32_t a0 = ldh2(&Ps[pr0 + kb + 2 * tig]);
            uint32_t a1 = ldh2(&Ps[pr1 + kb + 2 * tig]);
            uint32_t a2 = ldh2(&Ps[pr0 + kb + 8 + 2 * tig]);
            uint32_t a3 = ldh2(&Ps[pr1 + kb + 8 + 2 * tig]);
#pragma unroll
            for (int ni = 0; ni < 8; ni++) {
                uint32_t b0 = ldh2(&Vs[(ni * 8 + g) * AST + kb + 2 * tig]);
                uint32_t b1 = ldh2(&Vs[(ni * 8 + g) * AST + kb + 8 + 2 * tig]);
                mma_f16(o[ni], a0, a1, a2, a3, b0, b1);
            }
        }
    }

    // Epilogue
    const float inv0 = 1.f / l0;
    const float inv1 = 1.f / l1;
    const int row0 = qb * AQ + w * 16 + g;
#pragma unroll
    for (int ni = 0; ni < 8; ni++) {
        const int col = h * HD + ni * 8 + 2 * tig;
        *(float2*)&out[(size_t)row0 * DIM + col] =
            make_float2(o[ni][0] * inv0, o[ni][1] * inv0);
        *(float2*)&out[(size_t)(row0 + 8) * DIM + col] =
            make_float2(o[ni][2] * inv1, o[ni][3] * inv1);
    }
}

// ---------------------------------------------------------------------------
extern "C" void kernel_launch(void* const* d_in, const int* in_sizes, int n_in,
                              void* d_out, int out_size)
{
    const float* x      = (const float*)d_in[0];
    const float* W_qkv  = (const float*)d_in[1];
    const float* W_proj = (const float*)d_in[2];
    const float* b_proj = (const float*)d_in[3];
    float* out = (float*)d_out;

    float* qkv; cudaGetSymbolAddress((void**)&qkv, g_qkv);
    float* att; cudaGetSymbolAddress((void**)&att, g_att);

    // 1) qkv = x @ W_qkv^T
    {
        dim3 grid(C3 / BN, SEQ / BM);
        gemm_f16<<<grid, 256>>>(x, W_qkv, nullptr, qkv, SEQ, C3, C3);
    }
    // 2) attention
    {
        dim3 grid(SEQ / AQ, NHEAD);
        attn_f16<<<grid, 128>>>(qkv, att);
    }
    // 3) out = att @ W_proj^T + b_proj
    {
        dim3 grid(DIM / BN, SEQ / BM);
        gemm_f16<<<grid, 256>>>(att, W_proj, b_proj, out, SEQ, DIM, DIM);
    }
}

// round 7
// speedup vs baseline: 1.5778x; 1.1169x over previous
#include <cuda_runtime.h>
#include <cuda_fp16.h>
#include <math.h>
#include <stdint.h>

// Problem constants
#define SEQ   4096
#define DIM   1024
#define C3    3072
#define NHEAD 16
#define HD    64
#define SCALE 0.125f

// fp16 staging buffers (device globals; allocation-free per harness rules)
__device__ __half g_xh[SEQ * C3];       // 24 MB
__device__ __half g_wqkvh[C3 * C3];     // 18 MB
__device__ __half g_qkvh[SEQ * C3];     // 24 MB
__device__ __half g_atth[SEQ * DIM];    //  8 MB
__device__ __half g_wprojh[DIM * DIM];  //  2 MB

// ---------------------------------------------------------------------------
// Helpers
// ---------------------------------------------------------------------------
__device__ __forceinline__ void mma_f16(float* c,
                                        uint32_t a0, uint32_t a1, uint32_t a2, uint32_t a3,
                                        uint32_t b0, uint32_t b1) {
    asm volatile(
        "mma.sync.aligned.m16n8k16.row.col.f32.f16.f16.f32 "
        "{%0,%1,%2,%3}, {%4,%5,%6,%7}, {%8,%9}, {%0,%1,%2,%3};"
        : "+f"(c[0]), "+f"(c[1]), "+f"(c[2]), "+f"(c[3])
        : "r"(a0), "r"(a1), "r"(a2), "r"(a3), "r"(b0), "r"(b1));
}

__device__ __forceinline__ uint32_t ldh2(const __half* p) {
    return *(const uint32_t*)p;
}

__device__ __forceinline__ void cp_async16(uint32_t smem_addr, const void* gptr) {
    asm volatile("cp.async.cg.shared.global [%0], [%1], 16;"
                 :: "r"(smem_addr), "l"(gptr) : "memory");
}
__device__ __forceinline__ uint32_t smem_u32(const void* p) {
    uint32_t a;
    asm("{ .reg .u64 t; cvta.to.shared.u64 t, %1; cvt.u32.u64 %0, t; }"
        : "=r"(a) : "l"(p));
    return a;
}

// ---------------------------------------------------------------------------
// fp32 -> fp16 converter (grid-stride over 8-element chunks)
// ---------------------------------------------------------------------------
__global__ void f2h_kernel(const float* __restrict__ src, __half* __restrict__ dst, int n8)
{
    int i = blockIdx.x * blockDim.x + threadIdx.x;
    if (i >= n8) return;
    const float4* s = (const float4*)(src + (size_t)i * 8);
    float4 a = s[0], b = s[1];
    __half2 h0 = __floats2half2_rn(a.x, a.y);
    __half2 h1 = __floats2half2_rn(a.z, a.w);
    __half2 h2 = __floats2half2_rn(b.x, b.y);
    __half2 h3 = __floats2half2_rn(b.z, b.w);
    uint4 o;
    o.x = *(uint32_t*)&h0; o.y = *(uint32_t*)&h1;
    o.z = *(uint32_t*)&h2; o.w = *(uint32_t*)&h3;
    *(uint4*)(dst + (size_t)i * 8) = o;
}

// ---------------------------------------------------------------------------
// FP16 GEMM, fp16 inputs, cp.async 3-stage pipeline.
// C[M,N] = A[M,K] @ B[N,K]^T. Output: Ch (fp16) or Cf (fp32, +bias).
// 256 threads = 8 warps (4m x 2n), CTA tile 128x128, BK=32 halves.
// smem stride 40 halves; fragment loads conflict-free (proven R6).
// Dynamic smem: 3 stages x (128+128)*40*2B = 61440 B.
// ---------------------------------------------------------------------------
#define BM 128
#define BN 128
#define BKH 32
#define SH 40
#define STAGES 3
#define STAGE_HALVES (2 * BM * SH)            // A then B, 10240 halves
#define GEMM_SMEM (STAGES * STAGE_HALVES * 2) // 61440 B

__global__ __launch_bounds__(256, 2)
void gemm_h(const __half* __restrict__ A, const __half* __restrict__ B,
            const float* __restrict__ bias, float* __restrict__ Cf,
            __half* __restrict__ Ch, int M, int N, int K)
{
    extern __shared__ __half sh[];

    const int bx = blockIdx.x;        // N tile
    const int by = blockIdx.y;        // M tile
    const int tid = threadIdx.x;
    const int lane = tid & 31;
    const int wid = tid >> 5;
    const int wm = wid >> 1;          // 0..3
    const int wn = wid & 1;           // 0..1
    const int g = lane >> 2;          // 0..7
    const int tig = lane & 3;         // 0..3

    const __half* Ab = A + (size_t)(by * BM) * K;
    const __half* Bb = B + (size_t)(bx * BN) * K;

    const uint32_t sbase = smem_u32(sh);

    float acc[2][8][4];
#pragma unroll
    for (int mi = 0; mi < 2; mi++)
#pragma unroll
        for (int ni = 0; ni < 8; ni++)
#pragma unroll
            for (int r = 0; r < 4; r++) acc[mi][ni][r] = 0.f;

    const int nIter = K / BKH;

    // Copy map: per stage, A = 512 16B-chunks (128 rows x 4), same for B.
    // chunk c: row = c>>2, cc = c&3. Thread does chunks tid, tid+256 for A and B.
#define ISSUE_STAGE(it, slot) do {                                              \
        const int k0 = (it) * BKH;                                              \
        const uint32_t sA = sbase + (slot) * STAGE_HALVES * 2;                  \
        const uint32_t sB = sA + BM * SH * 2;                                   \
        _Pragma("unroll")                                                       \
        for (int p = 0; p < 2; p++) {                                           \
            const int c = tid + p * 256;                                        \
            const int r = c >> 2, cc = c & 3;                                   \
            cp_async16(sA + r * (SH * 2) + cc * 16,                             \
                       Ab + (size_t)r * K + k0 + cc * 8);                       \
            cp_async16(sB + r * (SH * 2) + cc * 16,                             \
                       Bb + (size_t)r * K + k0 + cc * 8);                       \
        }                                                                       \
    } while (0)

    // Prologue: stages 0..STAGES-2
#pragma unroll
    for (int s = 0; s < STAGES - 1; s++) {
        ISSUE_STAGE(s, s);
        asm volatile("cp.async.commit_group;" ::: "memory");
    }

    for (int it = 0; it < nIter; it++) {
        asm volatile("cp.async.wait_group %0;" :: "n"(STAGES - 2) : "memory");
        __syncthreads();

        // Issue stage it+STAGES-1 (empty commit keeps group accounting at tail)
        if (it + STAGES - 1 < nIter) {
            ISSUE_STAGE(it + STAGES - 1, (it + STAGES - 1) % STAGES);
        }
        asm volatile("cp.async.commit_group;" ::: "memory");

        // Compute stage it%STAGES
        const __half* As = sh + (it % STAGES) * STAGE_HALVES;
        const __half* Bs = As + BM * SH;
#pragma unroll
        for (int ks = 0; ks < 2; ks++) {
            const int kb = ks * 16;
            uint32_t af[2][4];
#pragma unroll
            for (int mi = 0; mi < 2; mi++) {
                const int rbm = wm * 32 + mi * 16;
                af[mi][0] = ldh2(&As[(rbm + g) * SH + kb + 2 * tig]);
                af[mi][1] = ldh2(&As[(rbm + g + 8) * SH + kb + 2 * tig]);
                af[mi][2] = ldh2(&As[(rbm + g) * SH + kb + 8 + 2 * tig]);
                af[mi][3] = ldh2(&As[(rbm + g + 8) * SH + kb + 8 + 2 * tig]);
            }
            uint32_t bf[8][2];
#pragma unroll
            for (int ni = 0; ni < 8; ni++) {
                const int nb = wn * 64 + ni * 8;
                bf[ni][0] = ldh2(&Bs[(nb + g) * SH + kb + 2 * tig]);
                bf[ni][1] = ldh2(&Bs[(nb + g) * SH + kb + 8 + 2 * tig]);
            }
#pragma unroll
            for (int mi = 0; mi < 2; mi++)
#pragma unroll
                for (int ni = 0; ni < 8; ni++)
                    mma_f16(acc[mi][ni], af[mi][0], af[mi][1], af[mi][2], af[mi][3],
                            bf[ni][0], bf[ni][1]);
        }
        __syncthreads();
    }
#undef ISSUE_STAGE

    // Epilogue
#pragma unroll
    for (int mi = 0; mi < 2; mi++) {
#pragma unroll
        for (int ni = 0; ni < 8; ni++) {
            const int row0 = by * BM + wm * 32 + mi * 16 + g;
            const int col = bx * BN + wn * 64 + ni * 8 + 2 * tig;
            if (Ch) {
                __half2 v0 = __floats2half2_rn(acc[mi][ni][0], acc[mi][ni][1]);
                __half2 v1 = __floats2half2_rn(acc[mi][ni][2], acc[mi][ni][3]);
                *(uint32_t*)&Ch[(size_t)row0 * N + col] = *(uint32_t*)&v0;
                *(uint32_t*)&Ch[(size_t)(row0 + 8) * N + col] = *(uint32_t*)&v1;
            } else {
                float b0 = 0.f, b1 = 0.f;
                if (bias) { b0 = bias[col]; b1 = bias[col + 1]; }
                *(float2*)&Cf[(size_t)row0 * N + col] =
                    make_float2(acc[mi][ni][0] + b0, acc[mi][ni][1] + b1);
                *(float2*)&Cf[(size_t)(row0 + 8) * N + col] =
                    make_float2(acc[mi][ni][2] + b0, acc[mi][ni][3] + b1);
            }
        }
    }
}

// ---------------------------------------------------------------------------
// Flash attention, fp16 in / fp16 out. Grid (SEQ/64, NHEAD), 128 threads.
// Same structure as R6 (proven), qkv now fp16.
// ---------------------------------------------------------------------------
#define AQ 64
#define AK 64
#define AST 72

__global__ __launch_bounds__(128, 4)
void attn_f16(const __half* __restrict__ qkv, __half* __restrict__ out)
{
    __shared__ __align__(16) __half Qs[AQ * AST];
    __shared__ __align__(16) __half Ks[AK * AST];
    __shared__ __align__(16) __half Ps[AQ * AST];
    __shared__ __align__(16) __half Vs[HD * AST];   // [hd][key]

    const int h = blockIdx.y;
    const int qb = blockIdx.x;
    const int tid = threadIdx.x;
    const int lane = tid & 31;
    const int w = tid >> 5;
    const int g = lane >> 2;
    const int tig = lane & 3;

    const int qcol = h * HD;
    const int kcol = DIM + h * HD;
    const int vcol = 2 * DIM + h * HD;

    // Load Q (scaled). 64 rows x 8 uint4; 4 per thread.
    const __half2 sc2 = __half2half2(__float2half(SCALE));
    for (int idx = tid; idx < AQ * HD / 8; idx += 128) {
        const int r = idx >> 3;
        const int c8 = idx & 7;
        uint4 v = *(const uint4*)&qkv[(size_t)(qb * AQ + r) * C3 + qcol + c8 * 8];
        __half2* hv = (__half2*)&v;
#pragma unroll
        for (int j = 0; j < 4; j++) hv[j] = __hmul2(hv[j], sc2);
        *(uint4*)&Qs[r * AST + c8 * 8] = v;
    }
    __syncthreads();

    // Hoist Q fragments: 4 k-steps of 16
    uint32_t qf[4][4];
    const int rb = w * 16;
#pragma unroll
    for (int ks = 0; ks < 4; ks++) {
        const int kb = ks * 16;
        qf[ks][0] = ldh2(&Qs[(rb + g) * AST + kb + 2 * tig]);
        qf[ks][1] = ldh2(&Qs[(rb + g + 8) * AST + kb + 2 * tig]);
        qf[ks][2] = ldh2(&Qs[(rb + g) * AST + kb + 8 + 2 * tig]);
        qf[ks][3] = ldh2(&Qs[(rb + g + 8) * AST + kb + 8 + 2 * tig]);
    }

    float m0 = -1e30f, m1 = -1e30f, l0 = 0.f, l1 = 0.f;
    float o[8][4];
#pragma unroll
    for (int ni = 0; ni < 8; ni++)
#pragma unroll
        for (int r = 0; r < 4; r++) o[ni][r] = 0.f;

    for (int kt = 0; kt < SEQ / AK; kt++) {
        __syncthreads();
        // K rows direct; V transposed ([hd][key])
        for (int idx = tid; idx < AK * HD / 8; idx += 128) {
            const int r = idx >> 3;
            const int c8 = idx & 7;
            const size_t ro = (size_t)(kt * AK + r) * C3;
            uint4 kv = *(const uint4*)&qkv[ro + kcol + c8 * 8];
            *(uint4*)&Ks[r * AST + c8 * 8] = kv;
            uint4 vv = *(const uint4*)&qkv[ro + vcol + c8 * 8];
            const __half* hv = (const __half*)&vv;
#pragma unroll
            for (int j = 0; j < 8; j++)
                Vs[(c8 * 8 + j) * AST + r] = hv[j];
        }
        __syncthreads();

        // S = Q K^T : 16x64 per warp
        float s[8][4];
#pragma unroll
        for (int ni = 0; ni < 8; ni++)
#pragma unroll
            for (int r = 0; r < 4; r++) s[ni][r] = 0.f;

#pragma unroll
        for (int ks = 0; ks < 4; ks++) {
            const int kb = ks * 16;
            uint32_t bf[8][2];
#pragma unroll
            for (int ni = 0; ni < 8; ni++) {
                bf[ni][0] = ldh2(&Ks[(ni * 8 + g) * AST + kb + 2 * tig]);
                bf[ni][1] = ldh2(&Ks[(ni * 8 + g) * AST + kb + 8 + 2 * tig]);
            }
#pragma unroll
            for (int ni = 0; ni < 8; ni++)
                mma_f16(s[ni], qf[ks][0], qf[ks][1], qf[ks][2], qf[ks][3],
                        bf[ni][0], bf[ni][1]);
        }

        // Online softmax
        float mx0 = -1e30f, mx1 = -1e30f;
#pragma unroll
        for (int ni = 0; ni < 8; ni++) {
            mx0 = fmaxf(mx0, fmaxf(s[ni][0], s[ni][1]));
            mx1 = fmaxf(mx1, fmaxf(s[ni][2], s[ni][3]));
        }
#pragma unroll
        for (int off = 1; off < 4; off <<= 1) {
            mx0 = fmaxf(mx0, __shfl_xor_sync(0xffffffffu, mx0, off));
            mx1 = fmaxf(mx1, __shfl_xor_sync(0xffffffffu, mx1, off));
        }
        const float nm0 = fmaxf(m0, mx0);
        const float nm1 = fmaxf(m1, mx1);
        const float al0 = __expf(m0 - nm0);
        const float al1 = __expf(m1 - nm1);
        m0 = nm0; m1 = nm1;

        float rs0 = 0.f, rs1 = 0.f;
        const int pr0 = (w * 16 + g) * AST;
        const int pr1 = (w * 16 + g + 8) * AST;
#pragma unroll
        for (int ni = 0; ni < 8; ni++) {
            const float p0 = __expf(s[ni][0] - nm0);
            const float p1 = __expf(s[ni][1] - nm0);
            const float p2 = __expf(s[ni][2] - nm1);
            const float p3 = __expf(s[ni][3] - nm1);
            rs0 += p0 + p1;
            rs1 += p2 + p3;
            const int c = ni * 8 + 2 * tig;
            __half2 h01 = __floats2half2_rn(p0, p1);
            __half2 h23 = __floats2half2_rn(p2, p3);
            *(uint32_t*)&Ps[pr0 + c] = *(uint32_t*)&h01;
            *(uint32_t*)&Ps[pr1 + c] = *(uint32_t*)&h23;
        }
#pragma unroll
        for (int off = 1; off < 4; off <<= 1) {
            rs0 += __shfl_xor_sync(0xffffffffu, rs0, off);
            rs1 += __shfl_xor_sync(0xffffffffu, rs1, off);
        }
        l0 = l0 * al0 + rs0;
        l1 = l1 * al1 + rs1;
#pragma unroll
        for (int ni = 0; ni < 8; ni++) {
            o[ni][0] *= al0; o[ni][1] *= al0;
            o[ni][2] *= al1; o[ni][3] *= al1;
        }
        __syncwarp();

        // O += P V
#pragma unroll
        for (int ks = 0; ks < 4; ks++) {
            const int kb = ks * 16;
            uint32_t a0 = ldh2(&Ps[pr0 + kb + 2 * tig]);
            uint32_t a1 = ldh2(&Ps[pr1 + kb + 2 * tig]);
            uint32_t a2 = ldh2(&Ps[pr0 + kb + 8 + 2 * tig]);
            uint32_t a3 = ldh2(&Ps[pr1 + kb + 8 + 2 * tig]);
#pragma unroll
            for (int ni = 0; ni < 8; ni++) {
                uint32_t b0 = ldh2(&Vs[(ni * 8 + g) * AST + kb + 2 * tig]);
                uint32_t b1 = ldh2(&Vs[(ni * 8 + g) * AST + kb + 8 + 2 * tig]);
                mma_f16(o[ni], a0, a1, a2, a3, b0, b1);
            }
        }
    }

    // Epilogue: fp16 out
    const float inv0 = 1.f / l0;
    const float inv1 = 1.f / l1;
    const int row0 = qb * AQ + w * 16 + g;
#pragma unroll
    for (int ni = 0; ni < 8; ni++) {
        const int col = h * HD + ni * 8 + 2 * tig;
        __half2 v0 = __floats2half2_rn(o[ni][0] * inv0, o[ni][1] * inv0);
        __half2 v1 = __floats2half2_rn(o[ni][2] * inv1, o[ni][3] * inv1);
        *(uint32_t*)&out[(size_t)row0 * DIM + col] = *(uint32_t*)&v0;
        *(uint32_t*)&out[(size_t)(row0 + 8) * DIM + col] = *(uint32_t*)&v1;
    }
}

// ---------------------------------------------------------------------------
extern "C" void kernel_launch(void* const* d_in, const int* in_sizes, int n_in,
                              void* d_out, int out_size)
{
    const float* x      = (const float*)d_in[0];
    const float* W_qkv  = (const float*)d_in[1];
    const float* W_proj = (const float*)d_in[2];
    const float* b_proj = (const float*)d_in[3];
    float* out = (float*)d_out;

    __half *xh, *wqkvh, *qkvh, *atth, *wprojh;
    cudaGetSymbolAddress((void**)&xh, g_xh);
    cudaGetSymbolAddress((void**)&wqkvh, g_wqkvh);
    cudaGetSymbolAddress((void**)&qkvh, g_qkvh);
    cudaGetSymbolAddress((void**)&atth, g_atth);
    cudaGetSymbolAddress((void**)&wprojh, g_wprojh);

    cudaFuncSetAttribute(gemm_h, cudaFuncAttributeMaxDynamicSharedMemorySize, GEMM_SMEM);

    // 0) fp32 -> fp16 conversions
    {
        int n8 = SEQ * C3 / 8;
        f2h_kernel<<<(n8 + 255) / 256, 256>>>(x, xh, n8);
        n8 = C3 * C3 / 8;
        f2h_kernel<<<(n8 + 255) / 256, 256>>>(W_qkv, wqkvh, n8);
        n8 = DIM * DIM / 8;
        f2h_kernel<<<(n8 + 255) / 256, 256>>>(W_proj, wprojh, n8);
    }
    // 1) qkv = x @ W_qkv^T  (fp16 out)
    {
        dim3 grid(C3 / BN, SEQ / BM);
        gemm_h<<<grid, 256, GEMM_SMEM>>>(xh, wqkvh, nullptr, nullptr, qkvh, SEQ, C3, C3);
    }
    // 2) attention (fp16 in/out)
    {
        dim3 grid(SEQ / AQ, NHEAD);
        attn_f16<<<grid, 128>>>(qkvh, atth);
    }
    // 3) out = att @ W_proj^T + b_proj  (fp32 out)
    {
        dim3 grid(DIM / BN, SEQ / BM);
        gemm_h<<<grid, 256, GEMM_SMEM>>>(atth, wprojh, b_proj, out, nullptr, SEQ, DIM, DIM);
    }
}

// round 8
// speedup vs baseline: 2.4312x; 1.5409x over previous
#include <cuda_runtime.h>
#include <cuda_fp16.h>
#include <math.h>
#include <stdint.h>

// Problem constants
#define SEQ   4096
#define DIM   1024
#define C3    3072
#define NHEAD 16
#define HD    64
#define SCALE 0.125f

// fp16 staging buffers (device globals; allocation-free per harness rules)
__device__ __half g_xh[SEQ * C3];       // 24 MB
__device__ __half g_wqkvh[C3 * C3];     // 18 MB
__device__ __half g_qkvh[SEQ * C3];     // 24 MB
__device__ __half g_atth[SEQ * DIM];    //  8 MB
__device__ __half g_wprojh[DIM * DIM];  //  2 MB

// ---------------------------------------------------------------------------
// Helpers
// ---------------------------------------------------------------------------
__device__ __forceinline__ void mma_f16(float* c,
                                        uint32_t a0, uint32_t a1, uint32_t a2, uint32_t a3,
                                        uint32_t b0, uint32_t b1) {
    asm volatile(
        "mma.sync.aligned.m16n8k16.row.col.f32.f16.f16.f32 "
        "{%0,%1,%2,%3}, {%4,%5,%6,%7}, {%8,%9}, {%0,%1,%2,%3};"
        : "+f"(c[0]), "+f"(c[1]), "+f"(c[2]), "+f"(c[3])
        : "r"(a0), "r"(a1), "r"(a2), "r"(a3), "r"(b0), "r"(b1));
}

__device__ __forceinline__ void ldm_x4(uint32_t& r0, uint32_t& r1,
                                       uint32_t& r2, uint32_t& r3, uint32_t addr) {
    asm volatile("ldmatrix.sync.aligned.m8n8.x4.shared.b16 {%0,%1,%2,%3}, [%4];"
                 : "=r"(r0), "=r"(r1), "=r"(r2), "=r"(r3) : "r"(addr));
}
__device__ __forceinline__ void ldm_x4_t(uint32_t& r0, uint32_t& r1,
                                         uint32_t& r2, uint32_t& r3, uint32_t addr) {
    asm volatile("ldmatrix.sync.aligned.m8n8.x4.trans.shared.b16 {%0,%1,%2,%3}, [%4];"
                 : "=r"(r0), "=r"(r1), "=r"(r2), "=r"(r3) : "r"(addr));
}

__device__ __forceinline__ void cp_async16(uint32_t smem_addr, const void* gptr) {
    asm volatile("cp.async.cg.shared.global [%0], [%1], 16;"
                 :: "r"(smem_addr), "l"(gptr) : "memory");
}
__device__ __forceinline__ uint32_t smem_u32(const void* p) {
    uint32_t a;
    asm("{ .reg .u64 t; cvta.to.shared.u64 t, %1; cvt.u32.u64 %0, t; }"
        : "=r"(a) : "l"(p));
    return a;
}

// ---------------------------------------------------------------------------
// fp32 -> fp16 converter
// ---------------------------------------------------------------------------
__global__ void f2h_kernel(const float* __restrict__ src, __half* __restrict__ dst, int n8)
{
    int i = blockIdx.x * blockDim.x + threadIdx.x;
    if (i >= n8) return;
    const float4* s = (const float4*)(src + (size_t)i * 8);
    float4 a = s[0], b = s[1];
    __half2 h0 = __floats2half2_rn(a.x, a.y);
    __half2 h1 = __floats2half2_rn(a.z, a.w);
    __half2 h2 = __floats2half2_rn(b.x, b.y);
    __half2 h3 = __floats2half2_rn(b.z, b.w);
    uint4 o;
    o.x = *(uint32_t*)&h0; o.y = *(uint32_t*)&h1;
    o.z = *(uint32_t*)&h2; o.w = *(uint32_t*)&h3;
    *(uint4*)(dst + (size_t)i * 8) = o;
}

// ---------------------------------------------------------------------------
// FP16 GEMM, cp.async 3-stage pipeline + ldmatrix fragment loads.
// C[M,N] = A[M,K] @ B[N,K]^T. Output: Ch (fp16) or Cf (fp32, +bias).
// 256 threads = 8 warps (4m x 2n), CTA tile 128x128, BK=32 halves, stride 40.
// ---------------------------------------------------------------------------
#define BM 128
#define BN 128
#define BKH 32
#define SH 40
#define STAGES 3
#define STAGE_HALVES (2 * BM * SH)
#define GEMM_SMEM (STAGES * STAGE_HALVES * 2)

__global__ __launch_bounds__(256, 2)
void gemm_h(const __half* __restrict__ A, const __half* __restrict__ B,
            const float* __restrict__ bias, float* __restrict__ Cf,
            __half* __restrict__ Ch, int M, int N, int K)
{
    extern __shared__ __half sh[];

    const int bx = blockIdx.x;
    const int by = blockIdx.y;
    const int tid = threadIdx.x;
    const int lane = tid & 31;
    const int wid = tid >> 5;
    const int wm = wid >> 1;          // 0..3
    const int wn = wid & 1;           // 0..1
    const int g = lane >> 2;
    const int tig = lane & 3;
    const int grp = lane >> 3;        // ldmatrix tile group
    const int lr = lane & 7;

    // ldmatrix per-lane row/col offsets (halves)
    const int rowA = (grp & 1) * 8 + lr;   // A tiles: m offset
    const int colA = (grp >> 1) * 8;       // A tiles: k offset
    const int rowB = (grp >> 1) * 8 + lr;  // B tiles: n offset
    const int colB = (grp & 1) * 8;        // B tiles: k offset

    const __half* Ab = A + (size_t)(by * BM) * K;
    const __half* Bb = B + (size_t)(bx * BN) * K;

    const uint32_t sbase = smem_u32(sh);

    float acc[2][8][4];
#pragma unroll
    for (int mi = 0; mi < 2; mi++)
#pragma unroll
        for (int ni = 0; ni < 8; ni++)
#pragma unroll
            for (int r = 0; r < 4; r++) acc[mi][ni][r] = 0.f;

    const int nIter = K / BKH;

#define ISSUE_STAGE(it, slot) do {                                              \
        const int k0 = (it) * BKH;                                              \
        const uint32_t sA = sbase + (slot) * STAGE_HALVES * 2;                  \
        const uint32_t sB = sA + BM * SH * 2;                                   \
        _Pragma("unroll")                                                       \
        for (int p = 0; p < 2; p++) {                                           \
            const int c = tid + p * 256;                                        \
            const int r = c >> 2, cc = c & 3;                                   \
            cp_async16(sA + r * (SH * 2) + cc * 16,                             \
                       Ab + (size_t)r * K + k0 + cc * 8);                       \
            cp_async16(sB + r * (SH * 2) + cc * 16,                             \
                       Bb + (size_t)r * K + k0 + cc * 8);                       \
        }                                                                       \
    } while (0)

#pragma unroll
    for (int s = 0; s < STAGES - 1; s++) {
        ISSUE_STAGE(s, s);
        asm volatile("cp.async.commit_group;" ::: "memory");
    }

    for (int it = 0; it < nIter; it++) {
        asm volatile("cp.async.wait_group %0;" :: "n"(STAGES - 2) : "memory");
        __syncthreads();

        if (it + STAGES - 1 < nIter) {
            ISSUE_STAGE(it + STAGES - 1, (it + STAGES - 1) % STAGES);
        }
        asm volatile("cp.async.commit_group;" ::: "memory");

        const uint32_t sA = sbase + (it % STAGES) * STAGE_HALVES * 2;
        const uint32_t sB = sA + BM * SH * 2;
#pragma unroll
        for (int ks = 0; ks < 2; ks++) {
            const int kb = ks * 16;
            uint32_t af[2][4];
#pragma unroll
            for (int mi = 0; mi < 2; mi++) {
                const int rbm = wm * 32 + mi * 16;
                ldm_x4(af[mi][0], af[mi][1], af[mi][2], af[mi][3],
                       sA + ((rbm + rowA) * SH + kb + colA) * 2);
            }
            uint32_t bf[8][2];
#pragma unroll
            for (int nip = 0; nip < 8; nip += 2) {
                ldm_x4(bf[nip][0], bf[nip][1], bf[nip + 1][0], bf[nip + 1][1],
                       sB + ((wn * 64 + nip * 8 + rowB) * SH + kb + colB) * 2);
            }
#pragma unroll
            for (int mi = 0; mi < 2; mi++)
#pragma unroll
                for (int ni = 0; ni < 8; ni++)
                    mma_f16(acc[mi][ni], af[mi][0], af[mi][1], af[mi][2], af[mi][3],
                            bf[ni][0], bf[ni][1]);
        }
        __syncthreads();
    }
#undef ISSUE_STAGE

    // Epilogue
#pragma unroll
    for (int mi = 0; mi < 2; mi++) {
#pragma unroll
        for (int ni = 0; ni < 8; ni++) {
            const int row0 = by * BM + wm * 32 + mi * 16 + g;
            const int col = bx * BN + wn * 64 + ni * 8 + 2 * tig;
            if (Ch) {
                __half2 v0 = __floats2half2_rn(acc[mi][ni][0], acc[mi][ni][1]);
                __half2 v1 = __floats2half2_rn(acc[mi][ni][2], acc[mi][ni][3]);
                *(uint32_t*)&Ch[(size_t)row0 * N + col] = *(uint32_t*)&v0;
                *(uint32_t*)&Ch[(size_t)(row0 + 8) * N + col] = *(uint32_t*)&v1;
            } else {
                float b0 = 0.f, b1 = 0.f;
                if (bias) { b0 = bias[col]; b1 = bias[col + 1]; }
                *(float2*)&Cf[(size_t)row0 * N + col] =
                    make_float2(acc[mi][ni][0] + b0, acc[mi][ni][1] + b1);
                *(float2*)&Cf[(size_t)(row0 + 8) * N + col] =
                    make_float2(acc[mi][ni][2] + b0, acc[mi][ni][3] + b1);
            }
        }
    }
}

// ---------------------------------------------------------------------------
// Flash attention: fp16 in/out, cp.async double-buffered K/V, ldmatrix frags.
// Grid (SEQ/64, NHEAD), 128 threads (4 warps), warp = 16 q-rows, 64-key tiles.
// Smem: QPs (Q, reused as P after hoist) + Ks[2] + Vs[2], all [64][72] halves.
// V stays row-major [key][hd]; PV B-frags via ldmatrix.x4.trans.
// ---------------------------------------------------------------------------
#define AQ 64
#define AK 64
#define AST 72
#define ATILE (AK * AST)

__global__ __launch_bounds__(128, 4)
void attn_f16(const __half* __restrict__ qkv, __half* __restrict__ out)
{
    __shared__ __align__(16) __half QPs[ATILE];
    __shared__ __align__(16) __half Ks[2][ATILE];
    __shared__ __align__(16) __half Vs[2][ATILE];

    const int h = blockIdx.y;
    const int qb = blockIdx.x;
    const int tid = threadIdx.x;
    const int lane = tid & 31;
    const int w = tid >> 5;
    const int g = lane >> 2;
    const int tig = lane & 3;
    const int grp = lane >> 3;
    const int lr = lane & 7;

    const int rowA = (grp & 1) * 8 + lr;   // A/P/Q tiles: m offset
    const int colA = (grp >> 1) * 8;       // A/P/Q tiles: k offset
    const int rowB = (grp >> 1) * 8 + lr;  // K tiles: n(key) offset
    const int colB = (grp & 1) * 8;        // K tiles: k(hd) offset
    const int rowV = (grp & 1) * 8 + lr;   // V trans tiles: k(key) offset
    const int colV = (grp >> 1) * 8;       // V trans tiles: n(hd) offset

    const uint32_t qp_u = smem_u32(QPs);
    const uint32_t k_u[2] = { smem_u32(Ks[0]), smem_u32(Ks[1]) };
    const uint32_t v_u[2] = { smem_u32(Vs[0]), smem_u32(Vs[1]) };

    const int qcol = h * HD;
    const int kcol = DIM + h * HD;
    const int vcol = 2 * DIM + h * HD;

    // Load Q (scaled) into QPs
    const __half2 sc2 = __half2half2(__float2half(SCALE));
    for (int idx = tid; idx < AQ * HD / 8; idx += 128) {
        const int r = idx >> 3;
        const int c8 = idx & 7;
        uint4 v = *(const uint4*)&qkv[(size_t)(qb * AQ + r) * C3 + qcol + c8 * 8];
        __half2* hv = (__half2*)&v;
#pragma unroll
        for (int j = 0; j < 4; j++) hv[j] = __hmul2(hv[j], sc2);
        *(uint4*)&QPs[r * AST + c8 * 8] = v;
    }
    __syncthreads();

    // Hoist Q fragments via ldmatrix (4 k-steps of 16)
    uint32_t qf[4][4];
    const int rb = w * 16;
#pragma unroll
    for (int ks = 0; ks < 4; ks++) {
        const int kb = ks * 16;
        ldm_x4(qf[ks][0], qf[ks][1], qf[ks][2], qf[ks][3],
               qp_u + ((rb + rowA) * AST + kb + colA) * 2);
    }
    __syncthreads();   // all warps hoisted; QPs can become P

    float m0 = -1e30f, m1 = -1e30f, l0 = 0.f, l1 = 0.f;
    float o[8][4];
#pragma unroll
    for (int ni = 0; ni < 8; ni++)
#pragma unroll
        for (int r = 0; r < 4; r++) o[ni][r] = 0.f;

    // cp.async K/V tile issue: 512 chunks of 16B per tile, 4 per thread each
#define ISSUE_KV(kt, st) do {                                                   \
        _Pragma("unroll")                                                       \
        for (int p = 0; p < 4; p++) {                                           \
            const int c = tid + p * 128;                                        \
            const int r = c >> 3, c8 = c & 7;                                   \
            const size_t ro = (size_t)((kt) * AK + r) * C3;                     \
            cp_async16(k_u[st] + (r * AST + c8 * 8) * 2, qkv + ro + kcol + c8 * 8); \
            cp_async16(v_u[st] + (r * AST + c8 * 8) * 2, qkv + ro + vcol + c8 * 8); \
        }                                                                       \
    } while (0)

    ISSUE_KV(0, 0);
    asm volatile("cp.async.commit_group;" ::: "memory");

    const int pr0 = (w * 16 + g) * AST;
    const int pr1 = (w * 16 + g + 8) * AST;

    for (int kt = 0; kt < SEQ / AK; kt++) {
        const int cur = kt & 1;
        asm volatile("cp.async.wait_group 0;" ::: "memory");
        __syncthreads();

        if (kt + 1 < SEQ / AK) {
            ISSUE_KV(kt + 1, cur ^ 1);
        }
        asm volatile("cp.async.commit_group;" ::: "memory");

        // S = Q K^T : 16x64 per warp
        float s[8][4];
#pragma unroll
        for (int ni = 0; ni < 8; ni++)
#pragma unroll
            for (int r = 0; r < 4; r++) s[ni][r] = 0.f;

#pragma unroll
        for (int ks = 0; ks < 4; ks++) {
            const int kb = ks * 16;
            uint32_t bf[8][2];
#pragma unroll
            for (int nip = 0; nip < 8; nip += 2) {
                ldm_x4(bf[nip][0], bf[nip][1], bf[nip + 1][0], bf[nip + 1][1],
                       k_u[cur] + ((nip * 8 + rowB) * AST + kb + colB) * 2);
            }
#pragma unroll
            for (int ni = 0; ni < 8; ni++)
                mma_f16(s[ni], qf[ks][0], qf[ks][1], qf[ks][2], qf[ks][3],
                        bf[ni][0], bf[ni][1]);
        }

        // Online softmax
        float mx0 = -1e30f, mx1 = -1e30f;
#pragma unroll
        for (int ni = 0; ni < 8; ni++) {
            mx0 = fmaxf(mx0, fmaxf(s[ni][0], s[ni][1]));
            mx1 = fmaxf(mx1, fmaxf(s[ni][2], s[ni][3]));
        }
#pragma unroll
        for (int off = 1; off < 4; off <<= 1) {
            mx0 = fmaxf(mx0, __shfl_xor_sync(0xffffffffu, mx0, off));
            mx1 = fmaxf(mx1, __shfl_xor_sync(0xffffffffu, mx1, off));
        }
        const float nm0 = fmaxf(m0, mx0);
        const float nm1 = fmaxf(m1, mx1);
        const float al0 = __expf(m0 - nm0);
        const float al1 = __expf(m1 - nm1);
        m0 = nm0; m1 = nm1;

        float rs0 = 0.f, rs1 = 0.f;
#pragma unroll
        for (int ni = 0; ni < 8; ni++) {
            const float p0 = __expf(s[ni][0] - nm0);
            const float p1 = __expf(s[ni][1] - nm0);
            const float p2 = __expf(s[ni][2] - nm1);
            const float p3 = __expf(s[ni][3] - nm1);
            rs0 += p0 + p1;
            rs1 += p2 + p3;
            const int c = ni * 8 + 2 * tig;
            __half2 h01 = __floats2half2_rn(p0, p1);
            __half2 h23 = __floats2half2_rn(p2, p3);
            *(uint32_t*)&QPs[pr0 + c] = *(uint32_t*)&h01;
            *(uint32_t*)&QPs[pr1 + c] = *(uint32_t*)&h23;
        }
#pragma unroll
        for (int off = 1; off < 4; off <<= 1) {
            rs0 += __shfl_xor_sync(0xffffffffu, rs0, off);
            rs1 += __shfl_xor_sync(0xffffffffu, rs1, off);
        }
        l0 = l0 * al0 + rs0;
        l1 = l1 * al1 + rs1;
#pragma unroll
        for (int ni = 0; ni < 8; ni++) {
            o[ni][0] *= al0; o[ni][1] *= al0;
            o[ni][2] *= al1; o[ni][3] *= al1;
        }
        __syncwarp();   // P rows warp-private

        // O += P V : A via ldmatrix on P, B via ldmatrix.trans on row-major V
#pragma unroll
        for (int ks = 0; ks < 4; ks++) {
            const int kb = ks * 16;
            uint32_t a0, a1, a2, a3;
            ldm_x4(a0, a1, a2, a3, qp_u + ((rb + rowA) * AST + kb + colA) * 2);
            uint32_t bv[8][2];
#pragma unroll
            for (int nip = 0; nip < 8; nip += 2) {
                ldm_x4_t(bv[nip][0], bv[nip][1], bv[nip + 1][0], bv[nip + 1][1],
                         v_u[cur] + ((kb + rowV) * AST + nip * 8 + colV) * 2);
            }
#pragma unroll
            for (int ni = 0; ni < 8; ni++)
                mma_f16(o[ni], a0, a1, a2, a3, bv[ni][0], bv[ni][1]);
        }
    }
#undef ISSUE_KV

    // Epilogue: fp16 out
    const float inv0 = 1.f / l0;
    const float inv1 = 1.f / l1;
    const int row0 = qb * AQ + w * 16 + g;
#pragma unroll
    for (int ni = 0; ni < 8; ni++) {
        const int col = h * HD + ni * 8 + 2 * tig;
        __half2 v0 = __floats2half2_rn(o[ni][0] * inv0, o[ni][1] * inv0);
        __half2 v1 = __floats2half2_rn(o[ni][2] * inv1, o[ni][3] * inv1);
        *(uint32_t*)&out[(size_t)row0 * DIM + col] = *(uint32_t*)&v0;
        *(uint32_t*)&out[(size_t)(row0 + 8) * DIM + col] = *(uint32_t*)&v1;
    }
}

// ---------------------------------------------------------------------------
extern "C" void kernel_launch(void* const* d_in, const int* in_sizes, int n_in,
                              void* d_out, int out_size)
{
    const float* x      = (const float*)d_in[0];
    const float* W_qkv  = (const float*)d_in[1];
    const float* W_proj = (const float*)d_in[2];
    const float* b_proj = (const float*)d_in[3];
    float* out = (float*)d_out;

    __half *xh, *wqkvh, *qkvh, *atth, *wprojh;
    cudaGetSymbolAddress((void**)&xh, g_xh);
    cudaGetSymbolAddress((void**)&wqkvh, g_wqkvh);
    cudaGetSymbolAddress((void**)&qkvh, g_qkvh);
    cudaGetSymbolAddress((void**)&atth, g_atth);
    cudaGetSymbolAddress((void**)&wprojh, g_wprojh);

    cudaFuncSetAttribute(gemm_h, cudaFuncAttributeMaxDynamicSharedMemorySize, GEMM_SMEM);

    // 0) fp32 -> fp16 conversions
    {
        int n8 = SEQ * C3 / 8;
        f2h_kernel<<<(n8 + 255) / 256, 256>>>(x, xh, n8);
        n8 = C3 * C3 / 8;
        f2h_kernel<<<(n8 + 255) / 256, 256>>>(W_qkv, wqkvh, n8);
        n8 = DIM * DIM / 8;
        f2h_kernel<<<(n8 + 255) / 256, 256>>>(W_proj, wprojh, n8);
    }
    // 1) qkv = x @ W_qkv^T  (fp16 out)
    {
        dim3 grid(C3 / BN, SEQ / BM);
        gemm_h<<<grid, 256, GEMM_SMEM>>>(xh, wqkvh, nullptr, nullptr, qkvh, SEQ, C3, C3);
    }
    // 2) attention (fp16 in/out)
    {
        dim3 grid(SEQ / AQ, NHEAD);
        attn_f16<<<grid, 128>>>(qkvh, atth);
    }
    // 3) out = att @ W_proj^T + b_proj  (fp32 out)
    {
        dim3 grid(DIM / BN, SEQ / BM);
        gemm_h<<<grid, 256, GEMM_SMEM>>>(atth, wprojh, b_proj, out, nullptr, SEQ, DIM, DIM);
    }
}